// round 17
// baseline (speedup 1.0000x reference)
#include <cuda_runtime.h>
#include <cuda_fp16.h>
#include <cstdint>

#define NTHREADS 256
#define TILE_B   16
#define NBLOCKS  (4096 / TILE_B)   // 256

// smem layout (bytes)
#define XROW_B  176                // fp16 row stride (44 words ≡ 12 mod 32: ldmatrix conflict-free)
#define XS_BUFB (16 * XROW_B)      // 2816 B per warp per buffer
#define OFB_XS  0                  // 8 warps * 2 bufs * 2816 = 45056
#define OFB_H1  45056              // half [16][1032] = 33024
#define OFB_H2  78080              // half [16][136]  = 4352
#define SMEM_BYTES 82432
#define SH1_STRB 2064
#define SH2_STRB 272

// Fragment-ordered weights (pre-scaled: W0f*0.5, others*0.25) + bias tables
__device__ __align__(16) uint2  g_W0f[512 * 32];
__device__ __align__(16) float4 g_c0f[512 * 4];      // (Wg,bg,W0 fold)*0.5
__device__ __align__(16) uint4  g_W1f[64 * 32 * 8];  // W1*0.25
__device__ __align__(16) uint4  g_W2f[8 * 32 * 8];   // W2*0.25
__device__ __align__(16) uint4  g_W3f[32 * 8];       // W3*0.25
__device__ __align__(16) float4 g_c1f[64 * 4];       // colsum(W1)/4
__device__ __align__(16) float4 g_c2f[8 * 4];        // colsum(W2)/4
__device__ __align__(16) float4 g_c3f[4];            // colsum(W3)/4

__device__ __forceinline__ unsigned h2bits(__half2 h) { return *(unsigned*)&h; }

// packed raw tanh: half2 bits of tanh(a), tanh(b)
__device__ __forceinline__ unsigned tanh2(float a, float b) {
    unsigned hv = h2bits(__floats2half2_rn(a, b)), t;
    asm("tanh.approx.f16x2 %0, %1;" : "=r"(t) : "r"(hv));
    return t;
}

__device__ __forceinline__ void mma16816(float& c0, float& c1, float& c2, float& c3,
                                         unsigned a0, unsigned a1, unsigned a2, unsigned a3,
                                         unsigned b0, unsigned b1) {
    asm("mma.sync.aligned.m16n8k16.row.col.f32.f16.f16.f32 "
        "{%0,%1,%2,%3},{%4,%5,%6,%7},{%8,%9},{%0,%1,%2,%3};"
        : "+f"(c0), "+f"(c1), "+f"(c2), "+f"(c3)
        : "r"(a0), "r"(a1), "r"(a2), "r"(a3), "r"(b0), "r"(b1));
}
__device__ __forceinline__ void mma1688(float& c0, float& c1, float& c2, float& c3,
                                        unsigned a0, unsigned a1, unsigned b0) {
    asm("mma.sync.aligned.m16n8k8.row.col.f32.f16.f16.f32 "
        "{%0,%1,%2,%3},{%4,%5},{%6},{%0,%1,%2,%3};"
        : "+f"(c0), "+f"(c1), "+f"(c2), "+f"(c3)
        : "r"(a0), "r"(a1), "r"(b0));
}
__device__ __forceinline__ void ldmA(unsigned& r0, unsigned& r1, unsigned& r2, unsigned& r3,
                                     uint32_t addr) {
    asm volatile("ldmatrix.sync.aligned.m8n8.x4.shared.b16 {%0,%1,%2,%3},[%4];"
                 : "=r"(r0), "=r"(r1), "=r"(r2), "=r"(r3) : "r"(addr));
}
__device__ __forceinline__ void ldmA2(unsigned& r0, unsigned& r1, uint32_t addr) {
    asm volatile("ldmatrix.sync.aligned.m8n8.x2.shared.b16 {%0,%1},[%2];"
                 : "=r"(r0), "=r"(r1) : "r"(addr));
}

// ---------------------------------------------------------------------------
// Prep: fragment-ordered, pre-scaled fp16 weights + bias tables
// ---------------------------------------------------------------------------
__global__ void prep_frags(const float* __restrict__ Wg,
                           const float* __restrict__ bg,
                           const float* __restrict__ W0,
                           const float* __restrict__ W1,
                           const float* __restrict__ W2,
                           const float* __restrict__ W3) {
    int idx = blockIdx.x * blockDim.x + threadIdx.x;
    if (idx < 512 * 32) {                       // W0f = (Wg*W0)*0.5
        int m = idx >> 5, lane = idx & 31;
        int k0 = (lane & 3) * 2, n = lane >> 2;
        const float* src = W0 + m * 128;        // [g][h]
        float g0 = 0.5f * Wg[m * 8 + k0], g1 = 0.5f * Wg[m * 8 + k0 + 1];
        __half2 f0 = __floats2half2_rn(g0 * src[k0 * 16 + n],
                                       g1 * src[(k0 + 1) * 16 + n]);
        __half2 f1 = __floats2half2_rn(g0 * src[k0 * 16 + n + 8],
                                       g1 * src[(k0 + 1) * 16 + n + 8]);
        uint2 v; v.x = h2bits(f0); v.y = h2bits(f1);
        g_W0f[idx] = v;
        return;
    }
    int t = idx - 512 * 32;
    if (t < 512 * 4) {                          // c0f = 0.5 * sum_g bg*W0
        int m = t >> 2, qq = t & 3;
        float s0 = 0.f, s1 = 0.f, s2 = 0.f, s3 = 0.f;
#pragma unroll
        for (int g = 0; g < 8; ++g) {
            float b = 0.5f * bg[m * 8 + g];
            const float* wr = W0 + m * 128 + g * 16;
            s0 += b * wr[qq * 2];     s1 += b * wr[qq * 2 + 1];
            s2 += b * wr[qq * 2 + 8]; s3 += b * wr[qq * 2 + 9];
        }
        float4 o; o.x = s0; o.y = s1; o.z = s2; o.w = s3;
        g_c0f[t] = o;
        return;
    }
    t -= 512 * 4;
    if (t < 73 * 32) {                          // W1f/W2f/W3f * 0.25
        int mod = t >> 5, lane = t & 31;
        const float* src; uint4* dst;
        if (mod < 64)      { src = W1 + mod * 2048;        dst = g_W1f + (size_t)(mod * 32 + lane) * 8; }
        else if (mod < 72) { src = W2 + (mod - 64) * 2048; dst = g_W2f + (size_t)((mod - 64) * 32 + lane) * 8; }
        else               { src = W3;                     dst = g_W3f + (size_t)lane * 8; }
#pragma unroll
        for (int kc = 0; kc < 8; ++kc) {
            uint4 o;
#pragma unroll
            for (int nh = 0; nh < 2; ++nh) {
                int k0 = kc * 16 + (lane & 3) * 2;
                int n  = nh * 8 + (lane >> 2);
                __half2 lo = __floats2half2_rn(0.25f * src[k0 * 16 + n],
                                               0.25f * src[(k0 + 1) * 16 + n]);
                __half2 hi = __floats2half2_rn(0.25f * src[(k0 + 8) * 16 + n],
                                               0.25f * src[(k0 + 9) * 16 + n]);
                if (nh == 0) { o.x = h2bits(lo); o.y = h2bits(hi); }
                else         { o.z = h2bits(lo); o.w = h2bits(hi); }
            }
            dst[kc] = o;
        }
        return;
    }
    t -= 73 * 32;
    if (t >= 73 * 4) return;                    // bias tables: colsum/4
    {
        int mod = t >> 2, qq = t & 3;
        const float* src; float4* dst;
        if (mod < 64)      { src = W1 + mod * 2048;        dst = g_c1f + mod * 4 + qq; }
        else if (mod < 72) { src = W2 + (mod - 64) * 2048; dst = g_c2f + (mod - 64) * 4 + qq; }
        else               { src = W3;                     dst = g_c3f + qq; }
        float s0 = 0.f, s1 = 0.f, s2 = 0.f, s3 = 0.f;
        for (int k = 0; k < 128; ++k) {
            const float* wr = src + k * 16;
            s0 += wr[qq * 2];     s1 += wr[qq * 2 + 1];
            s2 += wr[qq * 2 + 8]; s3 += wr[qq * 2 + 9];
        }
        float4 o; o.x = 0.25f * s0; o.y = 0.25f * s1; o.z = 0.25f * s2; o.w = 0.25f * s3;
        *dst = o;
    }
}

// ---------------------------------------------------------------------------
extern __shared__ __align__(16) char smem_raw[];

// 16x128x16 GEMM with bias-init accumulator (bias from c-frag float4)
__device__ __forceinline__ void gemm_16_128_16(uint32_t aAddr, const uint4* __restrict__ bp,
                                               float4 cf, float c[2][4]) {
    uint4 bv[8];
#pragma unroll
    for (int i = 0; i < 8; ++i) bv[i] = bp[i];
    c[0][0] = cf.x; c[0][1] = cf.y; c[0][2] = cf.x; c[0][3] = cf.y;
    c[1][0] = cf.z; c[1][1] = cf.w; c[1][2] = cf.z; c[1][3] = cf.w;
#pragma unroll
    for (int kc = 0; kc < 8; ++kc) {
        unsigned a0, a1, a2, a3;
        ldmA(a0, a1, a2, a3, aAddr + kc * 32);
        mma16816(c[0][0], c[0][1], c[0][2], c[0][3], a0, a1, a2, a3, bv[kc].x, bv[kc].y);
        mma16816(c[1][0], c[1][1], c[1][2], c[1][3], a0, a1, a2, a3, bv[kc].z, bv[kc].w);
    }
}

// store raw tanh(c) as half2 pairs
__device__ __forceinline__ void store_tanh_half(char* base, int strideB, int colBase,
                                                int lane, float c[2][4]) {
    int r0 = lane >> 2, cB = colBase + (lane & 3) * 2;
#pragma unroll
    for (int nh = 0; nh < 2; ++nh) {
        unsigned lo = tanh2(c[nh][0], c[nh][1]);
        unsigned hi = tanh2(c[nh][2], c[nh][3]);
        *(unsigned*)(base + r0 * strideB + (cB + nh * 8) * 2) = lo;
        *(unsigned*)(base + (r0 + 8) * strideB + (cB + nh * 8) * 2) = hi;
    }
}

__global__ void __launch_bounds__(NTHREADS, 2)
fused_kernel(const float* __restrict__ x,
             const float* __restrict__ Wf,
             float* __restrict__ out) {
    const int tid  = threadIdx.x;
    const int lane = tid & 31;
    const int w    = tid >> 5;          // warp 0..7
    const int b0   = blockIdx.x * TILE_B;

    const uint32_t sbase = (uint32_t)__cvta_generic_to_shared(smem_raw);

    const int r0 = lane >> 2;           // batch row (first of pair)
    const int q2 = (lane & 3) * 2;      // col pair within frag

    // coalesced x staging
    const int xrow = lane >> 4;         // 0..1
    const int xcol = lane & 15;         // float4 index within 64-float slice
    const float* xgw = x + ((size_t)b0 << 12) + w * 64;
    char* xbufs = smem_raw + OFB_XS + w * 2 * XS_BUFB;
    const uint32_t xldm = sbase + OFB_XS + w * 2 * XS_BUFB + (lane & 15) * XROW_B;

    uint4 xr[8];
#pragma unroll
    for (int g = 0; g < 8; ++g)
        xr[g] = *(const uint4*)(xgw + ((size_t)(g * 2 + xrow) << 12) + xcol * 4);
#pragma unroll
    for (int g = 0; g < 8; ++g) {
        float4 f = *(float4*)&xr[g];
        uint2 st;
        st.x = h2bits(__floats2half2_rn(f.x, f.y));
        st.y = h2bits(__floats2half2_rn(f.z, f.w));
        *(uint2*)(xbufs + (g * 2 + xrow) * XROW_B + xcol * 8) = st;
    }
    __syncwarp();

#pragma unroll 1
    for (int s2 = 0; s2 < 8; ++s2) {
        if (s2 < 7) {
            const float* src = xgw + (s2 + 1) * 512;
#pragma unroll
            for (int g = 0; g < 8; ++g)
                xr[g] = *(const uint4*)(src + ((size_t)(g * 2 + xrow) << 12) + xcol * 4);
        }
        uint4 bv[8];
        {
            const uint4* bp = g_W1f + (size_t)((s2 * 8 + w) * 32 + lane) * 8;
#pragma unroll
            for (int kc = 0; kc < 8; ++kc) bv[kc] = bp[kc];
        }

        const uint32_t xa = xldm + (s2 & 1) * XS_BUFB;

        // two independent accumulator chains (mm 0-3 and 4-7) for ILP
        float4 c1v = g_c1f[(s2 * 8 + w) * 4 + (lane & 3)];
        float accA[2][4], accB[2][4];
        accA[0][0] = c1v.x; accA[0][1] = c1v.y; accA[0][2] = c1v.x; accA[0][3] = c1v.y;
        accA[1][0] = c1v.z; accA[1][1] = c1v.w; accA[1][2] = c1v.z; accA[1][3] = c1v.w;
#pragma unroll
        for (int p = 0; p < 2; ++p)
#pragma unroll
            for (int q = 0; q < 4; ++q) accB[p][q] = 0.f;

#pragma unroll
        for (int mm = 0; mm < 8; ++mm) {
            const int m = s2 * 64 + w * 8 + mm;
            unsigned av0, av1;
            ldmA2(av0, av1, xa + mm * 16);
            float4 cf = g_c0f[m * 4 + (lane & 3)];
            uint2 bf = g_W0f[m * 32 + lane];
            float c0[4] = {cf.x, cf.y, cf.x, cf.y};
            float c1[4] = {cf.z, cf.w, cf.z, cf.w};
            mma1688(c0[0], c0[1], c0[2], c0[3], av0, av1, bf.x);
            mma1688(c1[0], c1[1], c1[2], c1[3], av0, av1, bf.y);
            unsigned f0 = tanh2(c0[0], c0[1]);
            unsigned f1 = tanh2(c0[2], c0[3]);
            unsigned f2 = tanh2(c1[0], c1[1]);
            unsigned f3 = tanh2(c1[2], c1[3]);
            float (*acc)[4] = (mm < 4) ? accA : accB;
            mma16816(acc[0][0], acc[0][1], acc[0][2], acc[0][3],
                     f0, f1, f2, f3, bv[mm].x, bv[mm].y);
            mma16816(acc[1][0], acc[1][1], acc[1][2], acc[1][3],
                     f0, f1, f2, f3, bv[mm].z, bv[mm].w);
        }
#pragma unroll
        for (int p = 0; p < 2; ++p)
#pragma unroll
            for (int q = 0; q < 4; ++q) accA[p][q] += accB[p][q];
        store_tanh_half(smem_raw + OFB_H1, SH1_STRB, s2 * 128 + w * 16, lane, accA);

        if (s2 < 7) {
            char* dst = xbufs + ((s2 + 1) & 1) * XS_BUFB;
#pragma unroll
            for (int g = 0; g < 8; ++g) {
                float4 f = *(float4*)&xr[g];
                uint2 st;
                st.x = h2bits(__floats2half2_rn(f.x, f.y));
                st.y = h2bits(__floats2half2_rn(f.z, f.w));
                *(uint2*)(dst + (g * 2 + xrow) * XROW_B + xcol * 8) = st;
            }
        }
        __syncwarp();
    }
    __syncthreads();   // H1 complete

    // ---- Level 2: warp w = subtree w ----
    {
        uint32_t aAddr = sbase + OFB_H1 + (lane & 15) * SH1_STRB
                       + (w * 128 + ((lane >> 4) * 8)) * 2;
        float c[2][4];
        gemm_16_128_16(aAddr, g_W2f + (size_t)(w * 32 + lane) * 8,
                       g_c2f[w * 4 + (lane & 3)], c);
        store_tanh_half(smem_raw + OFB_H2, SH2_STRB, w * 16, lane, c);
    }
    __syncthreads();   // H2 complete

    // ---- Root (warp 0): out = 0.5 * sum_h Wf_h * (t3_h + 1) ----
    if (w == 0) {
        uint32_t aAddr = sbase + OFB_H2 + (lane & 15) * SH2_STRB + ((lane >> 4) * 8) * 2;
        float c[2][4];
        gemm_16_128_16(aAddr, g_W3f + (size_t)lane * 8, g_c3f[lane & 3], c);
        float t0 = 0.f, t1 = 0.f;
#pragma unroll
        for (int nh = 0; nh < 2; ++nh) {
            float2 wf = __ldg((const float2*)(Wf + nh * 8 + q2));
            float t3a, t3b;
            asm("tanh.approx.f32 %0, %1;" : "=f"(t3a) : "f"(c[nh][0]));
            asm("tanh.approx.f32 %0, %1;" : "=f"(t3b) : "f"(c[nh][1]));
            t0 += wf.x * (t3a + 1.f) + wf.y * (t3b + 1.f);
            asm("tanh.approx.f32 %0, %1;" : "=f"(t3a) : "f"(c[nh][2]));
            asm("tanh.approx.f32 %0, %1;" : "=f"(t3b) : "f"(c[nh][3]));
            t1 += wf.x * (t3a + 1.f) + wf.y * (t3b + 1.f);
        }
        t0 += __shfl_xor_sync(0xffffffffu, t0, 1);
        t0 += __shfl_xor_sync(0xffffffffu, t0, 2);
        t1 += __shfl_xor_sync(0xffffffffu, t1, 1);
        t1 += __shfl_xor_sync(0xffffffffu, t1, 2);
        if ((lane & 3) == 0) {
            out[b0 + r0] = 0.5f * t0;
            out[b0 + 8 + r0] = 0.5f * t1;
        }
    }
}

// ---------------------------------------------------------------------------
extern "C" void kernel_launch(void* const* d_in, const int* in_sizes, int n_in,
                              void* d_out, int out_size) {
    const float* x  = (const float*)d_in[0];
    const float* Wg = (const float*)d_in[1];
    const float* bg = (const float*)d_in[2];
    const float* W0 = (const float*)d_in[3];
    const float* W1 = (const float*)d_in[4];
    const float* W2 = (const float*)d_in[5];
    const float* W3 = (const float*)d_in[6];
    const float* Wf = (const float*)d_in[7];
    float* out = (float*)d_out;

    cudaFuncSetAttribute(fused_kernel,
                         cudaFuncAttributeMaxDynamicSharedMemorySize, SMEM_BYTES);

    // 512*32 + 512*4 + 73*32 + 73*4 = 21060 items
    prep_frags<<<83, 256>>>(Wg, bg, W0, W1, W2, W3);
    fused_kernel<<<NBLOCKS, NTHREADS, SMEM_BYTES>>>(x, Wf, out);
}